// round 13
// baseline (speedup 1.0000x reference)
#include <cuda_runtime.h>
#include <cuda_bf16.h>
#include <mma.h>
#include <math.h>
#include <stdint.h>

using namespace nvcuda;

#define Bsz 128
#define PP 196
#define ENCD 2048
#define ATTD 512
#define EMBD 512
#define DECD 512
#define VV 30000
#define LL 22
#define TT 21
#define G4 2048
#define XR 3072   // emb(512) | ctx(2048) | h(512)

// output layout offsets (floats): outputs | caps | dec_lens | alphas | sort_ind
#define O_CAPS  80640000ll
#define O_DLEN  80642816ll
#define O_ALPHA 80642944ll
#define O_SORT  81169792ll

__device__ int   g_sort[Bsz];
__device__ int   g_dlen[Bsz];
__device__ int   g_caps[Bsz * LL];
__device__ __align__(16) float g_attn1[(size_t)Bsz * PP * ATTD];
__device__ __align__(16) float g_attn2[Bsz * ATTD];
__device__ __align__(16) float g_h[Bsz * DECD];
__device__ __align__(16) float g_c[Bsz * DECD];
__device__ __align__(16) float g_x[Bsz * XR];
__device__ __align__(16) float g_gpart[3][Bsz * G4];

__device__ __forceinline__ float sigmf_(float x) { return 1.f / (1.f + expf(-x)); }

__device__ __forceinline__ uint32_t pack_hi2(float x, float y) {
    __nv_bfloat162 t;
    t.x = __float2bfloat16(x);
    t.y = __float2bfloat16(y);
    return *reinterpret_cast<uint32_t*>(&t);
}
__device__ __forceinline__ uint32_t pack_lo2(float x, float y) {
    __nv_bfloat16 hx = __float2bfloat16(x), hy = __float2bfloat16(y);
    __nv_bfloat162 t;
    t.x = __float2bfloat16(x - __bfloat162float(hx));
    t.y = __float2bfloat16(y - __bfloat162float(hy));
    return *reinterpret_cast<uint32_t*>(&t);
}

// ================= setup kernels =================
__global__ void zero_out_kernel(float4* out4) {
    const size_t n1 = 20160000u;
    const size_t base2 = 20160736u;
    const size_t n2 = 131712u;
    size_t stride = (size_t)gridDim.x * blockDim.x;
    float4 z = make_float4(0.f, 0.f, 0.f, 0.f);
    for (size_t i = (size_t)blockIdx.x * blockDim.x + threadIdx.x; i < n1 + n2; i += stride) {
        size_t k = (i < n1) ? i : (base2 + (i - n1));
        out4[k] = z;
    }
}

__global__ void zero_state_kernel() {
    int stride = gridDim.x * blockDim.x;
    int i0 = blockIdx.x * blockDim.x + threadIdx.x;
    for (int i = i0; i < Bsz * DECD; i += stride) { g_h[i] = 0.f; g_c[i] = 0.f; }
    for (int i = i0; i < Bsz * XR; i += stride) g_x[i] = 0.f;
}

__global__ void sort_kernel(const int* __restrict__ clen,
                            const int* __restrict__ caps_in,
                            float* __restrict__ out) {
    __shared__ int s_len[Bsz];
    int i = threadIdx.x;
    s_len[i] = clen[i];
    __syncthreads();
    int li = s_len[i];
    int rank = 0;
    for (int j = 0; j < Bsz; j++) {
        int lj = s_len[j];
        rank += (lj > li) || (lj == li && j < i);
    }
    g_sort[rank] = i;
    g_dlen[rank] = li - 1;
    out[O_SORT + rank] = (float)i;
    out[O_DLEN + rank] = (float)(li - 1);
    __syncthreads();
    for (int k = i; k < Bsz * LL; k += Bsz) {
        int b = k / LL, j = k % LL;
        int v = caps_in[g_sort[b] * LL + j];
        g_caps[k] = v;
        out[O_CAPS + k] = (float)v;
    }
}

// ================= WMMA GEMM (128x128 C tile, R9 staging scheme) =============
// K chunks of 32; bf16 hi/lo 3-pass; fp32 accum; B from ORIGINAL fp32 weights.
//   MODE 0: attn1  A=enc(gathered)  B=We  [ENCD][ATTD] (transpose-stage, col_major frags)
//   MODE 1: attn2  A=g_h            B=Wd  [DECD][ATTD]
//   MODE 2: gates  A=g_x            B=Wih [2048][2560] & Whh [2048][512] ([N][K], direct rows)
//   MODE 3: fc     A=g_h            B=Wfc [DECD][VV], out=outputs (+bfc, row-masked)
// smem (bf16 elems): sA_hi [128][40] @0 | sA_lo @5120 | sB_hi [128][40] @10240 | sB_lo @15360
// total 40960B static. Epilogue reuses smem as 8x [32][32] f32 staging (two rounds).
template<int MODE, int KTOT, int KLEN, int NST>
__global__ void __launch_bounds__(256)
mma_gemm(const float* __restrict__ Afp,
         const float* __restrict__ W1, const float* __restrict__ W2,
         const float* __restrict__ b1,
         float* __restrict__ op, int t) {
    __shared__ __align__(16) char smem_raw[40960];
    __nv_bfloat16* sA_hi = (__nv_bfloat16*)smem_raw;   // [128][40]
    __nv_bfloat16* sA_lo = sA_hi + 5120;
    __nv_bfloat16* sB_hi = sA_hi + 10240;              // [128][40]
    __nv_bfloat16* sB_lo = sA_hi + 15360;

    int tid = threadIdx.x, lane = tid & 31, wid = tid >> 5;
    int wm = wid >> 1, wn = wid & 1;                   // 4 x 2 warp grid
    int n0 = blockIdx.x * 128;
    int m0 = (MODE == 0) ? (int)blockIdx.y * 128 : 0;
    int ks = (MODE == 2) ? (int)blockIdx.y : 0;
    int kbase = ks * KLEN;
    constexpr int NC = KLEN / 32;

    // A row pointers (fp32 sources) — identical to R9
    int arow_s = tid >> 3, ac4 = tid & 7;
    const float* aptr[4];
#pragma unroll
    for (int j = 0; j < 4; j++) {
        int row = arow_s + j * 32;
        if constexpr (MODE == 0) {
            int mg = m0 + row;
            aptr[j] = Afp + (size_t)g_sort[mg / PP] * (PP * ENCD) + (size_t)(mg % PP) * ENCD + kbase + ac4 * 4;
        } else if constexpr (MODE == 2) {
            aptr[j] = g_x + (size_t)row * XR + kbase + ac4 * 4;
        } else {
            aptr[j] = g_h + (size_t)row * DECD + kbase + ac4 * 4;
        }
    }
    int offAe[4];
#pragma unroll
    for (int j = 0; j < 4; j++) offAe[j] = (arow_s + j * 32) * 40 + ac4 * 4;

    wmma::fragment<wmma::accumulator, 16, 16, 16, float> C[2][4];
#pragma unroll
    for (int a = 0; a < 2; a++)
#pragma unroll
        for (int b = 0; b < 4; b++) wmma::fill_fragment(C[a][b], 0.f);

#pragma unroll 1
    for (int c = 0; c < NC; c++) {
        int kc = c * 32;
        // ---- stage A (fp32 -> bf16 hi/lo, wide stores) ----
#pragma unroll
        for (int j = 0; j < 4; j++) {
            float4 v = *(const float4*)(aptr[j] + kc);
            *(uint2*)(sA_hi + offAe[j]) = make_uint2(pack_hi2(v.x, v.y), pack_hi2(v.z, v.w));
            *(uint2*)(sA_lo + offAe[j]) = make_uint2(pack_lo2(v.x, v.y), pack_lo2(v.z, v.w));
        }
        // ---- stage B (128 n-rows) ----
        if constexpr (MODE == 2) {
            // W already [N][K]: direct rows, wide stores (R9 pattern, 128 rows)
#pragma unroll
            for (int r = 0; r < 4; r++) {
                int idx = tid + 256 * r;          // 0..1023
                int row = idx >> 3, c4 = idx & 7; // 128 rows x 8 float4
                int kg = kbase + kc + c4 * 4;
                const float* src = (kg < 2560) ? W1 + (size_t)(n0 + row) * 2560 + kg
                                               : W2 + (size_t)(n0 + row) * 512 + (kg - 2560);
                float4 v = *(const float4*)src;
                int o = row * 40 + c4 * 4;
                *(uint2*)(sB_hi + o) = make_uint2(pack_hi2(v.x, v.y), pack_hi2(v.z, v.w));
                *(uint2*)(sB_lo + o) = make_uint2(pack_lo2(v.x, v.y), pack_lo2(v.z, v.w));
            }
        } else {
            // W is [K][NST]: load [32k][128n] slab, transpose-scatter (R9 pattern)
#pragma unroll
            for (int r = 0; r < 4; r++) {
                int idx = tid + 256 * r;          // 0..1023
                int k = idx >> 5, nf4 = idx & 31; // 32 k-rows x 32 float4
                int n = nf4 * 4;
                float4 v = make_float4(0.f, 0.f, 0.f, 0.f);
                if constexpr (MODE == 3) {
                    int ng = n0 + n;
                    if (ng + 3 < NST) {
                        v = *(const float4*)(W1 + (size_t)(kbase + kc + k) * NST + ng);
                    } else {
                        float tmp[4] = {0.f, 0.f, 0.f, 0.f};
                        for (int i = 0; i < 4; i++)
                            if (ng + i < NST) tmp[i] = W1[(size_t)(kbase + kc + k) * NST + ng + i];
                        v = make_float4(tmp[0], tmp[1], tmp[2], tmp[3]);
                    }
                } else {
                    v = *(const float4*)(W1 + (size_t)(kbase + kc + k) * NST + n0 + n);
                }
                float vv[4] = {v.x, v.y, v.z, v.w};
#pragma unroll
                for (int i = 0; i < 4; i++) {
                    __nv_bfloat16 h = __float2bfloat16(vv[i]);
                    sB_hi[(n + i) * 40 + k] = h;
                    sB_lo[(n + i) * 40 + k] = __float2bfloat16(vv[i] - __bfloat162float(h));
                }
            }
        }
        __syncthreads();

        // ---- compute: 2 k16 steps, 3-pass hi/lo, col_major B ldm 40 ----
#pragma unroll
        for (int kk = 0; kk < 2; kk++) {
#pragma unroll
            for (int mf = 0; mf < 2; mf++) {
                wmma::fragment<wmma::matrix_a, 16, 16, 16, __nv_bfloat16, wmma::row_major> aH, aL;
                wmma::load_matrix_sync(aH, sA_hi + (wm * 32 + mf * 16) * 40 + kk * 16, 40);
                wmma::load_matrix_sync(aL, sA_lo + (wm * 32 + mf * 16) * 40 + kk * 16, 40);
#pragma unroll
                for (int nf = 0; nf < 4; nf++) {
                    wmma::fragment<wmma::matrix_b, 16, 16, 16, __nv_bfloat16, wmma::col_major> bH, bL;
                    wmma::load_matrix_sync(bH, sB_hi + (wn * 64 + nf * 16) * 40 + kk * 16, 40);
                    wmma::load_matrix_sync(bL, sB_lo + (wn * 64 + nf * 16) * 40 + kk * 16, 40);
                    wmma::mma_sync(C[mf][nf], aH, bH, C[mf][nf]);
                    wmma::mma_sync(C[mf][nf], aH, bL, C[mf][nf]);
                    wmma::mma_sync(C[mf][nf], aL, bH, C[mf][nf]);
                }
            }
        }
        __syncthreads();
    }

    // ---- epilogue: two rounds of per-warp [32][32] staging ----
    float* stg = (float*)smem_raw + wid * 1024;
#pragma unroll
    for (int p = 0; p < 2; p++) {
        wmma::store_matrix_sync(stg,                C[0][2 * p],     32, wmma::mem_row_major);
        wmma::store_matrix_sync(stg + 16,           C[0][2 * p + 1], 32, wmma::mem_row_major);
        wmma::store_matrix_sync(stg + 16 * 32,      C[1][2 * p],     32, wmma::mem_row_major);
        wmma::store_matrix_sync(stg + 16 * 32 + 16, C[1][2 * p + 1], 32, wmma::mem_row_major);
        __syncwarp();
#pragma unroll 4
        for (int e = lane; e < 1024; e += 32) {
            int rl = e >> 5, cl = e & 31;
            int gr = wm * 32 + rl;
            int n = n0 + wn * 64 + p * 32 + cl;
            float v = stg[e];
            if constexpr (MODE == 0) {
                g_attn1[(size_t)(m0 + gr) * ATTD + n] = v + b1[n];
            } else if constexpr (MODE == 1) {
                g_attn2[gr * ATTD + n] = v + b1[n];
            } else if constexpr (MODE == 2) {
                g_gpart[ks][gr * G4 + n] = v;
            } else {
                if (t < g_dlen[gr] && n < VV)
                    op[((size_t)gr * TT + t) * VV + n] = v + b1[n];
            }
        }
        __syncwarp();
    }
}

// ================= attention (fused e/softmax/alpha/ctx/emb) =================
__global__ void attention_kernel(const float* __restrict__ enc,
                                 const float* __restrict__ wf,
                                 const float* __restrict__ bfp,
                                 const float* __restrict__ emb_table,
                                 float* __restrict__ out, int t) {
    int b = blockIdx.x;
    if (t >= g_dlen[b]) return;
    int tid = threadIdx.x;
    int warp = tid >> 5, lane = tid & 31;
    __shared__ float s_a2[ATTD];
    __shared__ float s_e[PP];
    __shared__ float s_red[32];

    int cap = g_caps[b * LL + t];
    for (int i = tid; i < EMBD; i += 256)
        g_x[b * XR + i] = emb_table[(size_t)cap * EMBD + i];
    for (int i = tid; i < ATTD; i += 256) s_a2[i] = g_attn2[b * ATTD + i];
    __syncthreads();

    float bfv = bfp[0];
    const float* a1 = g_attn1 + (size_t)b * PP * ATTD;
    for (int p = warp; p < PP; p += 8) {
        const float* row = a1 + (size_t)p * ATTD;
        float s = 0.f;
        for (int a = lane; a < ATTD; a += 32) {
            float v = row[a] + s_a2[a];
            v = fmaxf(v, 0.f);
            s += v * wf[a];
        }
#pragma unroll
        for (int o = 16; o; o >>= 1) s += __shfl_xor_sync(0xffffffffu, s, o);
        if (lane == 0) s_e[p] = s + bfv;
    }
    __syncthreads();

    float mx = -1e30f;
    for (int p = tid; p < PP; p += 256) mx = fmaxf(mx, s_e[p]);
#pragma unroll
    for (int o = 16; o; o >>= 1) mx = fmaxf(mx, __shfl_xor_sync(0xffffffffu, mx, o));
    if (lane == 0) s_red[warp] = mx;
    __syncthreads();
    if (tid == 0) {
        float m2 = s_red[0];
        for (int w = 1; w < 8; w++) m2 = fmaxf(m2, s_red[w]);
        s_red[16] = m2;
    }
    __syncthreads();
    mx = s_red[16];
    float sum = 0.f;
    for (int p = tid; p < PP; p += 256) {
        float e = expf(s_e[p] - mx);
        s_e[p] = e;
        sum += e;
    }
#pragma unroll
    for (int o = 16; o; o >>= 1) sum += __shfl_xor_sync(0xffffffffu, sum, o);
    if (lane == 0) s_red[warp] = sum;
    __syncthreads();
    if (tid == 0) {
        float s2 = 0.f;
        for (int w = 0; w < 8; w++) s2 += s_red[w];
        s_red[17] = 1.f / s2;
    }
    __syncthreads();
    float inv = s_red[17];
    float* aout = out + O_ALPHA + ((size_t)b * TT + t) * PP;
    for (int p = tid; p < PP; p += 256) {
        float al = s_e[p] * inv;
        s_e[p] = al;
        aout[p] = al;
    }
    __syncthreads();

    const float* encb = enc + (size_t)g_sort[b] * (PP * ENCD);
    float acc[8];
#pragma unroll
    for (int j = 0; j < 8; j++) acc[j] = 0.f;
    for (int p = 0; p < PP; p++) {
        float al = s_e[p];
        const float* er = encb + (size_t)p * ENCD;
#pragma unroll
        for (int j = 0; j < 8; j++) acc[j] += al * er[tid + 256 * j];
    }
    float* xo = g_x + b * XR + EMBD;
#pragma unroll
    for (int j = 0; j < 8; j++) xo[tid + 256 * j] = acc[j];
}

// ================= LSTM pointwise (sums split-K partials + biases) ===========
__global__ void lstm_kernel(const float* __restrict__ bih, const float* __restrict__ bhh, int t) {
    int idx = blockIdx.x * blockDim.x + threadIdx.x;
    if (idx >= Bsz * DECD) return;
    int b = idx >> 9;
    if (t >= g_dlen[b]) return;
    int d = idx & 511;
    int base = b * G4;
    float gi = g_gpart[0][base + d]        + g_gpart[1][base + d]        + g_gpart[2][base + d]        + bih[d]        + bhh[d];
    float gf = g_gpart[0][base + d + 512]  + g_gpart[1][base + d + 512]  + g_gpart[2][base + d + 512]  + bih[d + 512]  + bhh[d + 512];
    float gg = g_gpart[0][base + d + 1024] + g_gpart[1][base + d + 1024] + g_gpart[2][base + d + 1024] + bih[d + 1024] + bhh[d + 1024];
    float go = g_gpart[0][base + d + 1536] + g_gpart[1][base + d + 1536] + g_gpart[2][base + d + 1536] + bih[d + 1536] + bhh[d + 1536];
    float c = g_c[idx];
    float cn = sigmf_(gf) * c + sigmf_(gi) * tanhf(gg);
    float hn = sigmf_(go) * tanhf(cn);
    g_c[idx] = cn;
    g_h[idx] = hn;
    g_x[b * XR + 2560 + d] = hn;
}

// ================= launch =================
extern "C" void kernel_launch(void* const* d_in, const int* in_sizes, int n_in,
                              void* d_out, int out_size) {
    const float* enc  = (const float*)d_in[0];
    const int*   caps = (const int*)d_in[1];
    const int*   clen = (const int*)d_in[2];
    const float* embt = (const float*)d_in[3];
    const float* We   = (const float*)d_in[4];
    const float* be   = (const float*)d_in[5];
    const float* Wd   = (const float*)d_in[6];
    const float* bd   = (const float*)d_in[7];
    const float* wf   = (const float*)d_in[8];
    const float* bf   = (const float*)d_in[9];
    const float* Wih  = (const float*)d_in[10];
    const float* bih  = (const float*)d_in[11];
    const float* Whh  = (const float*)d_in[12];
    const float* bhh  = (const float*)d_in[13];
    const float* Wfc  = (const float*)d_in[14];
    const float* bfc  = (const float*)d_in[15];
    float* out = (float*)d_out;

    zero_out_kernel<<<8192, 256>>>((float4*)out);
    zero_state_kernel<<<512, 256>>>();
    sort_kernel<<<1, 128>>>(clen, caps, out);

    // attn1 = enc_sorted @ We + be   (M=25088, N=512)
    mma_gemm<0, ENCD, ENCD, ATTD><<<dim3(4, 196), 256>>>(enc, We, nullptr, be, nullptr, 0);

    for (int t = 0; t < TT; t++) {
        mma_gemm<1, DECD, DECD, ATTD><<<dim3(4, 1), 256>>>(nullptr, Wd, nullptr, bd, nullptr, t);
        attention_kernel<<<128, 256>>>(enc, wf, bf, embt, out, t);
        mma_gemm<2, XR, 1024, 1><<<dim3(16, 3), 256>>>(nullptr, Wih, Whh, nullptr, nullptr, t);
        lstm_kernel<<<256, 256>>>(bih, bhh, t);
        mma_gemm<3, DECD, DECD, VV><<<dim3(235, 1), 256>>>(nullptr, Wfc, nullptr, bfc, out, t);
    }
}

// round 14
// speedup vs baseline: 1.2881x; 1.2881x over previous
#include <cuda_runtime.h>
#include <cuda_bf16.h>
#include <mma.h>
#include <math.h>
#include <stdint.h>

using namespace nvcuda;

#define Bsz 128
#define PP 196
#define ENCD 2048
#define ATTD 512
#define EMBD 512
#define DECD 512
#define VV 30000
#define LL 22
#define TT 21
#define G4 2048
#define XR 3072   // emb(512) | ctx(2048) | h(512)

// output layout offsets (floats): outputs | caps | dec_lens | alphas | sort_ind
#define O_CAPS  80640000ll
#define O_DLEN  80642816ll
#define O_ALPHA 80642944ll
#define O_SORT  81169792ll

__device__ int   g_sort[Bsz];
__device__ int   g_dlen[Bsz];
__device__ int   g_caps[Bsz * LL];
__device__ __align__(16) float g_attn1[(size_t)Bsz * PP * ATTD];
__device__ __align__(16) float g_attn2[Bsz * ATTD];
__device__ __align__(16) float g_h[Bsz * DECD];
__device__ __align__(16) float g_c[Bsz * DECD];
__device__ __align__(16) float g_x[Bsz * XR];
__device__ __align__(16) float g_gpart[3][Bsz * G4];

__device__ __forceinline__ float sigmf_(float x) { return 1.f / (1.f + expf(-x)); }

__device__ __forceinline__ uint32_t pack_hi2(float x, float y) {
    __nv_bfloat162 t;
    t.x = __float2bfloat16(x);
    t.y = __float2bfloat16(y);
    return *reinterpret_cast<uint32_t*>(&t);
}
__device__ __forceinline__ uint32_t pack_lo2(float x, float y) {
    __nv_bfloat16 hx = __float2bfloat16(x), hy = __float2bfloat16(y);
    __nv_bfloat162 t;
    t.x = __float2bfloat16(x - __bfloat162float(hx));
    t.y = __float2bfloat16(y - __bfloat162float(hy));
    return *reinterpret_cast<uint32_t*>(&t);
}

// ================= setup kernels =================
__global__ void zero_out_kernel(float4* out4) {
    const size_t n1 = 20160000u;
    const size_t base2 = 20160736u;
    const size_t n2 = 131712u;
    size_t stride = (size_t)gridDim.x * blockDim.x;
    float4 z = make_float4(0.f, 0.f, 0.f, 0.f);
    for (size_t i = (size_t)blockIdx.x * blockDim.x + threadIdx.x; i < n1 + n2; i += stride) {
        size_t k = (i < n1) ? i : (base2 + (i - n1));
        out4[k] = z;
    }
}

__global__ void zero_state_kernel() {
    int stride = gridDim.x * blockDim.x;
    int i0 = blockIdx.x * blockDim.x + threadIdx.x;
    for (int i = i0; i < Bsz * DECD; i += stride) { g_h[i] = 0.f; g_c[i] = 0.f; }
    for (int i = i0; i < Bsz * XR; i += stride) g_x[i] = 0.f;
}

__global__ void sort_kernel(const int* __restrict__ clen,
                            const int* __restrict__ caps_in,
                            float* __restrict__ out) {
    __shared__ int s_len[Bsz];
    int i = threadIdx.x;
    s_len[i] = clen[i];
    __syncthreads();
    int li = s_len[i];
    int rank = 0;
    for (int j = 0; j < Bsz; j++) {
        int lj = s_len[j];
        rank += (lj > li) || (lj == li && j < i);
    }
    g_sort[rank] = i;
    g_dlen[rank] = li - 1;
    out[O_SORT + rank] = (float)i;
    out[O_DLEN + rank] = (float)(li - 1);
    __syncthreads();
    for (int k = i; k < Bsz * LL; k += Bsz) {
        int b = k / LL, j = k % LL;
        int v = caps_in[g_sort[b] * LL + j];
        g_caps[k] = v;
        out[O_CAPS + k] = (float)v;
    }
}

// ================= WMMA GEMM (R9 base + occ bump + wide B staging + warp mask)
// C[128 x 64] per block; K chunks of 32; bf16 hi/lo 3-pass; fp32 accum.
// B staged on the fly from ORIGINAL fp32 weights:
//   MODE 0: attn1  A=enc(gathered)  B=We  [ENCD][ATTD]  -> col_major frags, ldm 40
//   MODE 1: attn2  A=g_h            B=Wd  [DECD][ATTD]
//   MODE 2: gates  A=g_x            B=Wih [2048][2560] & Whh [2048][512] ([N][K] direct)
//   MODE 3: fc     A=g_h            B=Wfc [DECD][VV], out=outputs (+bfc, row-masked)
// smem (bf16 elems): sA_hi [128][40] @0 | sA_lo @5120 | sB_hi [64][40] @10240 | sB_lo @12800
template<int MODE, int KTOT, int KLEN, int NST>
__global__ void __launch_bounds__(256, 3)
mma_gemm(const float* __restrict__ Afp,
         const float* __restrict__ W1, const float* __restrict__ W2,
         const float* __restrict__ b1,
         float* __restrict__ op, int t) {
    __shared__ __align__(16) char smem_raw[32768];
    __nv_bfloat16* sA_hi = (__nv_bfloat16*)smem_raw;   // [128][40]
    __nv_bfloat16* sA_lo = sA_hi + 5120;
    __nv_bfloat16* sB_hi = sA_hi + 10240;              // [64][40]
    __nv_bfloat16* sB_lo = sA_hi + 12800;

    int tid = threadIdx.x, lane = tid & 31, wid = tid >> 5;
    int wm = wid >> 1, wn = wid & 1;
    int n0 = blockIdx.x * 64;
    int m0 = (MODE == 0) ? (int)blockIdx.y * 128 : 0;
    int ks = (MODE == 2) ? (int)blockIdx.y : 0;
    int kbase = ks * KLEN;
    constexpr int NC = KLEN / 32;

    // warp activity (length-sorted rows): warp wm covers rows [wm*32, wm*32+32)
    bool my_act = (MODE == 0) ? true : (t < g_dlen[wm * 32]);
    bool row_act[4];   // for A staging: row group j -> warp j
#pragma unroll
    for (int j = 0; j < 4; j++)
        row_act[j] = (MODE == 0) ? true : (t < g_dlen[j * 32]);

    // A row pointers (fp32 sources) — R9 pattern
    int arow_s = tid >> 3, ac4 = tid & 7;
    const float* aptr[4];
#pragma unroll
    for (int j = 0; j < 4; j++) {
        int row = arow_s + j * 32;
        if constexpr (MODE == 0) {
            int mg = m0 + row;
            aptr[j] = Afp + (size_t)g_sort[mg / PP] * (PP * ENCD) + (size_t)(mg % PP) * ENCD + kbase + ac4 * 4;
        } else if constexpr (MODE == 2) {
            aptr[j] = g_x + (size_t)row * XR + kbase + ac4 * 4;
        } else {
            aptr[j] = g_h + (size_t)row * DECD + kbase + ac4 * 4;
        }
    }
    int offAe[4];
#pragma unroll
    for (int j = 0; j < 4; j++) offAe[j] = (arow_s + j * 32) * 40 + ac4 * 4;

    // B staging indices (MODE != 2): thread -> (n, k-octet)
    int bn = tid >> 2;     // 0..63
    int bkq = tid & 3;     // 0..3 (k-octet within 32-chunk)

    wmma::fragment<wmma::accumulator, 16, 16, 16, float> C[2][2];
#pragma unroll
    for (int a = 0; a < 2; a++)
#pragma unroll
        for (int b = 0; b < 2; b++) wmma::fill_fragment(C[a][b], 0.f);

#pragma unroll 1
    for (int c = 0; c < NC; c++) {
        int kc = c * 32;
        // ---- stage A (fp32 -> bf16 hi/lo, wide stores; skip inactive row groups) ----
#pragma unroll
        for (int j = 0; j < 4; j++) {
            if (row_act[j]) {
                float4 v = *(const float4*)(aptr[j] + kc);
                *(uint2*)(sA_hi + offAe[j]) = make_uint2(pack_hi2(v.x, v.y), pack_hi2(v.z, v.w));
                *(uint2*)(sA_lo + offAe[j]) = make_uint2(pack_lo2(v.x, v.y), pack_lo2(v.z, v.w));
            }
        }
        // ---- stage B ----
        if constexpr (MODE == 2) {
            // W already [N][K]: direct rows, wide stores (R9 pattern)
#pragma unroll
            for (int r = 0; r < 2; r++) {
                int idx = tid + 256 * r;          // 0..511
                int row = idx >> 3, c4 = idx & 7; // 64 rows x 8 float4
                int kg = kbase + kc + c4 * 4;
                const float* src = (kg < 2560) ? W1 + (size_t)(n0 + row) * 2560 + kg
                                               : W2 + (size_t)(n0 + row) * 512 + (kg - 2560);
                float4 v = *(const float4*)src;
                int o = row * 40 + c4 * 4;
                *(uint2*)(sB_hi + o) = make_uint2(pack_hi2(v.x, v.y), pack_hi2(v.z, v.w));
                *(uint2*)(sB_lo + o) = make_uint2(pack_lo2(v.x, v.y), pack_lo2(v.z, v.w));
            }
        } else {
            // W is [K][NST] row-major: 8 strided scalar loads (k-major gather) + 2 uint4 stores
            float bv[8];
            int ng = n0 + bn;
            bool ok = (MODE != 3) || (ng < NST);
            const float* wcol = W1 + (size_t)(kbase + kc + bkq * 8) * NST + ng;
#pragma unroll
            for (int i = 0; i < 8; i++)
                bv[i] = ok ? wcol[(size_t)i * NST] : 0.f;
            uint4 hv, lv;
            hv.x = pack_hi2(bv[0], bv[1]); hv.y = pack_hi2(bv[2], bv[3]);
            hv.z = pack_hi2(bv[4], bv[5]); hv.w = pack_hi2(bv[6], bv[7]);
            lv.x = pack_lo2(bv[0], bv[1]); lv.y = pack_lo2(bv[2], bv[3]);
            lv.z = pack_lo2(bv[4], bv[5]); lv.w = pack_lo2(bv[6], bv[7]);
            int o = bn * 40 + bkq * 8;
            *(uint4*)(sB_hi + o) = hv;
            *(uint4*)(sB_lo + o) = lv;
        }
        __syncthreads();

        // ---- compute: 2 k16 steps, 3-pass hi/lo (active warps only) ----
        if (my_act) {
#pragma unroll
            for (int kk = 0; kk < 2; kk++) {
#pragma unroll
                for (int mf = 0; mf < 2; mf++) {
                    wmma::fragment<wmma::matrix_a, 16, 16, 16, __nv_bfloat16, wmma::row_major> aH, aL;
                    wmma::load_matrix_sync(aH, sA_hi + (wm * 32 + mf * 16) * 40 + kk * 16, 40);
                    wmma::load_matrix_sync(aL, sA_lo + (wm * 32 + mf * 16) * 40 + kk * 16, 40);
#pragma unroll
                    for (int nf = 0; nf < 2; nf++) {
                        wmma::fragment<wmma::matrix_b, 16, 16, 16, __nv_bfloat16, wmma::col_major> bH, bL;
                        wmma::load_matrix_sync(bH, sB_hi + (wn * 32 + nf * 16) * 40 + kk * 16, 40);
                        wmma::load_matrix_sync(bL, sB_lo + (wn * 32 + nf * 16) * 40 + kk * 16, 40);
                        wmma::mma_sync(C[mf][nf], aH, bH, C[mf][nf]);
                        wmma::mma_sync(C[mf][nf], aH, bL, C[mf][nf]);
                        wmma::mma_sync(C[mf][nf], aL, bH, C[mf][nf]);
                    }
                }
            }
        }
        __syncthreads();
    }

    // ---- epilogue: per-warp smem staging then scalar stores (active warps) ----
    if (my_act) {
        float* stg = (float*)smem_raw + wid * 1024;   // [32][32] per warp
        wmma::store_matrix_sync(stg,                C[0][0], 32, wmma::mem_row_major);
        wmma::store_matrix_sync(stg + 16,           C[0][1], 32, wmma::mem_row_major);
        wmma::store_matrix_sync(stg + 16 * 32,      C[1][0], 32, wmma::mem_row_major);
        wmma::store_matrix_sync(stg + 16 * 32 + 16, C[1][1], 32, wmma::mem_row_major);
        __syncwarp();
#pragma unroll 4
        for (int e = lane; e < 1024; e += 32) {
            int rl = e >> 5, cl = e & 31;
            int gr = wm * 32 + rl;
            int n = n0 + wn * 32 + cl;
            float v = stg[e];
            if constexpr (MODE == 0) {
                g_attn1[(size_t)(m0 + gr) * ATTD + n] = v + b1[n];
            } else if constexpr (MODE == 1) {
                g_attn2[gr * ATTD + n] = v + b1[n];
            } else if constexpr (MODE == 2) {
                g_gpart[ks][gr * G4 + n] = v;
            } else {
                if (t < g_dlen[gr] && n < VV)
                    op[((size_t)gr * TT + t) * VV + n] = v + b1[n];
            }
        }
    }
}

// ================= attention (fused e/softmax/alpha/ctx/emb) =================
__global__ void attention_kernel(const float* __restrict__ enc,
                                 const float* __restrict__ wf,
                                 const float* __restrict__ bfp,
                                 const float* __restrict__ emb_table,
                                 float* __restrict__ out, int t) {
    int b = blockIdx.x;
    if (t >= g_dlen[b]) return;
    int tid = threadIdx.x;
    int warp = tid >> 5, lane = tid & 31;
    __shared__ float s_a2[ATTD];
    __shared__ float s_e[PP];
    __shared__ float s_red[32];

    int cap = g_caps[b * LL + t];
    for (int i = tid; i < EMBD; i += 256)
        g_x[b * XR + i] = emb_table[(size_t)cap * EMBD + i];
    for (int i = tid; i < ATTD; i += 256) s_a2[i] = g_attn2[b * ATTD + i];
    __syncthreads();

    float bfv = bfp[0];
    const float* a1 = g_attn1 + (size_t)b * PP * ATTD;
    for (int p = warp; p < PP; p += 8) {
        const float* row = a1 + (size_t)p * ATTD;
        float s = 0.f;
        for (int a = lane; a < ATTD; a += 32) {
            float v = row[a] + s_a2[a];
            v = fmaxf(v, 0.f);
            s += v * wf[a];
        }
#pragma unroll
        for (int o = 16; o; o >>= 1) s += __shfl_xor_sync(0xffffffffu, s, o);
        if (lane == 0) s_e[p] = s + bfv;
    }
    __syncthreads();

    float mx = -1e30f;
    for (int p = tid; p < PP; p += 256) mx = fmaxf(mx, s_e[p]);
#pragma unroll
    for (int o = 16; o; o >>= 1) mx = fmaxf(mx, __shfl_xor_sync(0xffffffffu, mx, o));
    if (lane == 0) s_red[warp] = mx;
    __syncthreads();
    if (tid == 0) {
        float m2 = s_red[0];
        for (int w = 1; w < 8; w++) m2 = fmaxf(m2, s_red[w]);
        s_red[16] = m2;
    }
    __syncthreads();
    mx = s_red[16];
    float sum = 0.f;
    for (int p = tid; p < PP; p += 256) {
        float e = expf(s_e[p] - mx);
        s_e[p] = e;
        sum += e;
    }
#pragma unroll
    for (int o = 16; o; o >>= 1) sum += __shfl_xor_sync(0xffffffffu, sum, o);
    if (lane == 0) s_red[warp] = sum;
    __syncthreads();
    if (tid == 0) {
        float s2 = 0.f;
        for (int w = 0; w < 8; w++) s2 += s_red[w];
        s_red[17] = 1.f / s2;
    }
    __syncthreads();
    float inv = s_red[17];
    float* aout = out + O_ALPHA + ((size_t)b * TT + t) * PP;
    for (int p = tid; p < PP; p += 256) {
        float al = s_e[p] * inv;
        s_e[p] = al;
        aout[p] = al;
    }
    __syncthreads();

    const float* encb = enc + (size_t)g_sort[b] * (PP * ENCD);
    float acc[8];
#pragma unroll
    for (int j = 0; j < 8; j++) acc[j] = 0.f;
    for (int p = 0; p < PP; p++) {
        float al = s_e[p];
        const float* er = encb + (size_t)p * ENCD;
#pragma unroll
        for (int j = 0; j < 8; j++) acc[j] += al * er[tid + 256 * j];
    }
    float* xo = g_x + b * XR + EMBD;
#pragma unroll
    for (int j = 0; j < 8; j++) xo[tid + 256 * j] = acc[j];
}

// ================= LSTM pointwise (sums split-K partials + biases) ===========
__global__ void lstm_kernel(const float* __restrict__ bih, const float* __restrict__ bhh, int t) {
    int idx = blockIdx.x * blockDim.x + threadIdx.x;
    if (idx >= Bsz * DECD) return;
    int b = idx >> 9;
    if (t >= g_dlen[b]) return;
    int d = idx & 511;
    int base = b * G4;
    float gi = g_gpart[0][base + d]        + g_gpart[1][base + d]        + g_gpart[2][base + d]        + bih[d]        + bhh[d];
    float gf = g_gpart[0][base + d + 512]  + g_gpart[1][base + d + 512]  + g_gpart[2][base + d + 512]  + bih[d + 512]  + bhh[d + 512];
    float gg = g_gpart[0][base + d + 1024] + g_gpart[1][base + d + 1024] + g_gpart[2][base + d + 1024] + bih[d + 1024] + bhh[d + 1024];
    float go = g_gpart[0][base + d + 1536] + g_gpart[1][base + d + 1536] + g_gpart[2][base + d + 1536] + bih[d + 1536] + bhh[d + 1536];
    float c = g_c[idx];
    float cn = sigmf_(gf) * c + sigmf_(gi) * tanhf(gg);
    float hn = sigmf_(go) * tanhf(cn);
    g_c[idx] = cn;
    g_h[idx] = hn;
    g_x[b * XR + 2560 + d] = hn;
}

// ================= launch =================
extern "C" void kernel_launch(void* const* d_in, const int* in_sizes, int n_in,
                              void* d_out, int out_size) {
    const float* enc  = (const float*)d_in[0];
    const int*   caps = (const int*)d_in[1];
    const int*   clen = (const int*)d_in[2];
    const float* embt = (const float*)d_in[3];
    const float* We   = (const float*)d_in[4];
    const float* be   = (const float*)d_in[5];
    const float* Wd   = (const float*)d_in[6];
    const float* bd   = (const float*)d_in[7];
    const float* wf   = (const float*)d_in[8];
    const float* bf   = (const float*)d_in[9];
    const float* Wih  = (const float*)d_in[10];
    const float* bih  = (const float*)d_in[11];
    const float* Whh  = (const float*)d_in[12];
    const float* bhh  = (const float*)d_in[13];
    const float* Wfc  = (const float*)d_in[14];
    const float* bfc  = (const float*)d_in[15];
    float* out = (float*)d_out;

    zero_out_kernel<<<8192, 256>>>((float4*)out);
    zero_state_kernel<<<512, 256>>>();
    sort_kernel<<<1, 128>>>(clen, caps, out);

    // attn1 = enc_sorted @ We + be   (M=25088, N=512)
    mma_gemm<0, ENCD, ENCD, ATTD><<<dim3(8, 196), 256>>>(enc, We, nullptr, be, nullptr, 0);

    for (int t = 0; t < TT; t++) {
        mma_gemm<1, DECD, DECD, ATTD><<<dim3(8, 1), 256>>>(nullptr, Wd, nullptr, bd, nullptr, t);
        attention_kernel<<<128, 256>>>(enc, wf, bf, embt, out, t);
        mma_gemm<2, XR, 1024, 1><<<dim3(32, 3), 256>>>(nullptr, Wih, Whh, nullptr, nullptr, t);
        lstm_kernel<<<256, 256>>>(bih, bhh, t);
        mma_gemm<3, DECD, DECD, VV><<<dim3(469, 1), 256>>>(nullptr, Wfc, nullptr, bfc, out, t);
    }
}

// round 15
// speedup vs baseline: 1.7255x; 1.3395x over previous
#include <cuda_runtime.h>
#include <cuda_bf16.h>
#include <mma.h>
#include <math.h>
#include <stdint.h>

using namespace nvcuda;

#define Bsz 128
#define PP 196
#define ENCD 2048
#define ATTD 512
#define EMBD 512
#define DECD 512
#define VV 30000
#define LL 22
#define TT 21
#define G4 2048
#define XR 3072   // emb(512) | ctx(2048) | h(512)

// output layout offsets (floats): outputs | caps | dec_lens | alphas | sort_ind
#define O_CAPS  80640000ll
#define O_DLEN  80642816ll
#define O_ALPHA 80642944ll
#define O_SORT  81169792ll

__device__ int   g_sort[Bsz];
__device__ int   g_dlen[Bsz];
__device__ int   g_caps[Bsz * LL];
__device__ __align__(16) float g_attn1[(size_t)Bsz * PP * ATTD];
__device__ __align__(16) float g_attn2[Bsz * ATTD];
__device__ __align__(16) float g_h[Bsz * DECD];
__device__ __align__(16) float g_c[Bsz * DECD];
__device__ __align__(16) float g_x[Bsz * XR];
__device__ __align__(16) float g_gpart[3][Bsz * G4];

__device__ __forceinline__ float sigmf_(float x) { return 1.f / (1.f + expf(-x)); }

__device__ __forceinline__ uint32_t pack_hi2(float x, float y) {
    __nv_bfloat162 t;
    t.x = __float2bfloat16(x);
    t.y = __float2bfloat16(y);
    return *reinterpret_cast<uint32_t*>(&t);
}
__device__ __forceinline__ uint32_t pack_lo2(float x, float y) {
    __nv_bfloat16 hx = __float2bfloat16(x), hy = __float2bfloat16(y);
    __nv_bfloat162 t;
    t.x = __float2bfloat16(x - __bfloat162float(hx));
    t.y = __float2bfloat16(y - __bfloat162float(hy));
    return *reinterpret_cast<uint32_t*>(&t);
}

// ================= setup kernels =================
__global__ void zero_out_kernel(float4* out4) {
    const size_t n1 = 20160000u;
    const size_t base2 = 20160736u;
    const size_t n2 = 131712u;
    size_t stride = (size_t)gridDim.x * blockDim.x;
    float4 z = make_float4(0.f, 0.f, 0.f, 0.f);
    for (size_t i = (size_t)blockIdx.x * blockDim.x + threadIdx.x; i < n1 + n2; i += stride) {
        size_t k = (i < n1) ? i : (base2 + (i - n1));
        out4[k] = z;
    }
}

__global__ void zero_state_kernel() {
    int stride = gridDim.x * blockDim.x;
    int i0 = blockIdx.x * blockDim.x + threadIdx.x;
    for (int i = i0; i < Bsz * DECD; i += stride) { g_h[i] = 0.f; g_c[i] = 0.f; }
    for (int i = i0; i < Bsz * XR; i += stride) g_x[i] = 0.f;
}

__global__ void sort_kernel(const int* __restrict__ clen,
                            const int* __restrict__ caps_in,
                            float* __restrict__ out) {
    __shared__ int s_len[Bsz];
    int i = threadIdx.x;
    s_len[i] = clen[i];
    __syncthreads();
    int li = s_len[i];
    int rank = 0;
    for (int j = 0; j < Bsz; j++) {
        int lj = s_len[j];
        rank += (lj > li) || (lj == li && j < i);
    }
    g_sort[rank] = i;
    g_dlen[rank] = li - 1;
    out[O_SORT + rank] = (float)i;
    out[O_DLEN + rank] = (float)(li - 1);
    __syncthreads();
    for (int k = i; k < Bsz * LL; k += Bsz) {
        int b = k / LL, j = k % LL;
        int v = caps_in[g_sort[b] * LL + j];
        g_caps[k] = v;
        out[O_CAPS + k] = (float)v;
    }
}

// ================= WMMA GEMM (R14 + software-pipelined staging) ==============
// C[128 x 64] per block; K chunks of 32; bf16 hi/lo 3-pass; fp32 accum.
// Chunk loop: [store staged regs] sync [issue loads c+1] compute(c) sync —
// global-load latency overlaps compute.
//   MODE 0: attn1  A=enc(gathered)  B=We  [ENCD][ATTD]  -> col_major frags, ldm 40
//   MODE 1: attn2  A=g_h            B=Wd  [DECD][ATTD]
//   MODE 2: gates  A=g_x            B=Wih [2048][2560] & Whh [2048][512] ([N][K] direct)
//   MODE 3: fc     A=g_h            B=Wfc [DECD][VV], out=outputs (+bfc, row-masked)
// smem (bf16 elems): sA_hi [128][40] @0 | sA_lo @5120 | sB_hi [64][40] @10240 | sB_lo @12800
template<int MODE, int KTOT, int KLEN, int NST>
__global__ void __launch_bounds__(256, 2)
mma_gemm(const float* __restrict__ Afp,
         const float* __restrict__ W1, const float* __restrict__ W2,
         const float* __restrict__ b1,
         float* __restrict__ op, int t) {
    __shared__ __align__(16) char smem_raw[32768];
    __nv_bfloat16* sA_hi = (__nv_bfloat16*)smem_raw;   // [128][40]
    __nv_bfloat16* sA_lo = sA_hi + 5120;
    __nv_bfloat16* sB_hi = sA_hi + 10240;              // [64][40]
    __nv_bfloat16* sB_lo = sA_hi + 12800;

    int tid = threadIdx.x, lane = tid & 31, wid = tid >> 5;
    int wm = wid >> 1, wn = wid & 1;
    int n0 = blockIdx.x * 64;
    int m0 = (MODE == 0) ? (int)blockIdx.y * 128 : 0;
    int ks = (MODE == 2) ? (int)blockIdx.y : 0;
    int kbase = ks * KLEN;
    constexpr int NC = KLEN / 32;

    // warp activity (length-sorted rows)
    bool my_act = (MODE == 0) ? true : (t < g_dlen[wm * 32]);
    bool row_act[4];
#pragma unroll
    for (int j = 0; j < 4; j++)
        row_act[j] = (MODE == 0) ? true : (t < g_dlen[j * 32]);

    // A row pointers
    int arow_s = tid >> 3, ac4 = tid & 7;
    const float* aptr[4];
#pragma unroll
    for (int j = 0; j < 4; j++) {
        int row = arow_s + j * 32;
        if constexpr (MODE == 0) {
            int mg = m0 + row;
            aptr[j] = Afp + (size_t)g_sort[mg / PP] * (PP * ENCD) + (size_t)(mg % PP) * ENCD + kbase + ac4 * 4;
        } else if constexpr (MODE == 2) {
            aptr[j] = g_x + (size_t)row * XR + kbase + ac4 * 4;
        } else {
            aptr[j] = g_h + (size_t)row * DECD + kbase + ac4 * 4;
        }
    }
    int offAe[4];
#pragma unroll
    for (int j = 0; j < 4; j++) offAe[j] = (arow_s + j * 32) * 40 + ac4 * 4;

    // B staging indices
    int bn = tid >> 2;     // MODE!=2: n index 0..63
    int bkq = tid & 3;     // k-octet
    int b2row = tid >> 3, b2c4 = tid & 7;   // MODE==2: 64 rows x 8 float4 (2 rounds)

    wmma::fragment<wmma::accumulator, 16, 16, 16, float> C[2][2];
#pragma unroll
    for (int a = 0; a < 2; a++)
#pragma unroll
        for (int b = 0; b < 2; b++) wmma::fill_fragment(C[a][b], 0.f);

    // ---- prefetch regs ----
    float4 avr[4];
    float bvr[8];      // MODE != 2
    float4 b2r[2];     // MODE == 2

    auto load_chunk = [&](int c) {
        int kc = c * 32;
#pragma unroll
        for (int j = 0; j < 4; j++)
            if (row_act[j]) avr[j] = *(const float4*)(aptr[j] + kc);
        if constexpr (MODE == 2) {
#pragma unroll
            for (int r = 0; r < 2; r++) {
                int row = b2row + r * 32;      // wait: need rows 0..63 over 2 rounds of 32? b2row is 0..31
                int kg = kbase + kc + b2c4 * 4;
                const float* src = (kg < 2560) ? W1 + (size_t)(n0 + row) * 2560 + kg
                                               : W2 + (size_t)(n0 + row) * 512 + (kg - 2560);
                b2r[r] = *(const float4*)src;
            }
        } else {
            int ng = n0 + bn;
            bool ok = (MODE != 3) || (ng < NST);
            const float* wcol = W1 + (size_t)(kbase + kc + bkq * 8) * NST + ng;
#pragma unroll
            for (int i = 0; i < 8; i++)
                bvr[i] = ok ? wcol[(size_t)i * NST] : 0.f;
        }
    };

    auto store_chunk = [&]() {
#pragma unroll
        for (int j = 0; j < 4; j++) {
            if (row_act[j]) {
                *(uint2*)(sA_hi + offAe[j]) = make_uint2(pack_hi2(avr[j].x, avr[j].y), pack_hi2(avr[j].z, avr[j].w));
                *(uint2*)(sA_lo + offAe[j]) = make_uint2(pack_lo2(avr[j].x, avr[j].y), pack_lo2(avr[j].z, avr[j].w));
            }
        }
        if constexpr (MODE == 2) {
#pragma unroll
            for (int r = 0; r < 2; r++) {
                int row = b2row + r * 32;
                int o = row * 40 + b2c4 * 4;
                *(uint2*)(sB_hi + o) = make_uint2(pack_hi2(b2r[r].x, b2r[r].y), pack_hi2(b2r[r].z, b2r[r].w));
                *(uint2*)(sB_lo + o) = make_uint2(pack_lo2(b2r[r].x, b2r[r].y), pack_lo2(b2r[r].z, b2r[r].w));
            }
        } else {
            uint4 hv, lv;
            hv.x = pack_hi2(bvr[0], bvr[1]); hv.y = pack_hi2(bvr[2], bvr[3]);
            hv.z = pack_hi2(bvr[4], bvr[5]); hv.w = pack_hi2(bvr[6], bvr[7]);
            lv.x = pack_lo2(bvr[0], bvr[1]); lv.y = pack_lo2(bvr[2], bvr[3]);
            lv.z = pack_lo2(bvr[4], bvr[5]); lv.w = pack_lo2(bvr[6], bvr[7]);
            int o = bn * 40 + bkq * 8;
            *(uint4*)(sB_hi + o) = hv;
            *(uint4*)(sB_lo + o) = lv;
        }
    };

    load_chunk(0);

#pragma unroll 1
    for (int c = 0; c < NC; c++) {
        store_chunk();
        __syncthreads();
        if (c + 1 < NC) load_chunk(c + 1);   // loads overlap compute below
        if (my_act) {
#pragma unroll
            for (int kk = 0; kk < 2; kk++) {
#pragma unroll
                for (int mf = 0; mf < 2; mf++) {
                    wmma::fragment<wmma::matrix_a, 16, 16, 16, __nv_bfloat16, wmma::row_major> aH, aL;
                    wmma::load_matrix_sync(aH, sA_hi + (wm * 32 + mf * 16) * 40 + kk * 16, 40);
                    wmma::load_matrix_sync(aL, sA_lo + (wm * 32 + mf * 16) * 40 + kk * 16, 40);
#pragma unroll
                    for (int nf = 0; nf < 2; nf++) {
                        wmma::fragment<wmma::matrix_b, 16, 16, 16, __nv_bfloat16, wmma::col_major> bH, bL;
                        wmma::load_matrix_sync(bH, sB_hi + (wn * 32 + nf * 16) * 40 + kk * 16, 40);
                        wmma::load_matrix_sync(bL, sB_lo + (wn * 32 + nf * 16) * 40 + kk * 16, 40);
                        wmma::mma_sync(C[mf][nf], aH, bH, C[mf][nf]);
                        wmma::mma_sync(C[mf][nf], aH, bL, C[mf][nf]);
                        wmma::mma_sync(C[mf][nf], aL, bH, C[mf][nf]);
                    }
                }
            }
        }
        __syncthreads();
    }

    // ---- epilogue ----
    if (my_act) {
        float* stg = (float*)smem_raw + wid * 1024;
        wmma::store_matrix_sync(stg,                C[0][0], 32, wmma::mem_row_major);
        wmma::store_matrix_sync(stg + 16,           C[0][1], 32, wmma::mem_row_major);
        wmma::store_matrix_sync(stg + 16 * 32,      C[1][0], 32, wmma::mem_row_major);
        wmma::store_matrix_sync(stg + 16 * 32 + 16, C[1][1], 32, wmma::mem_row_major);
        __syncwarp();
#pragma unroll 4
        for (int e = lane; e < 1024; e += 32) {
            int rl = e >> 5, cl = e & 31;
            int gr = wm * 32 + rl;
            int n = n0 + wn * 32 + cl;
            float v = stg[e];
            if constexpr (MODE == 0) {
                g_attn1[(size_t)(m0 + gr) * ATTD + n] = v + b1[n];
            } else if constexpr (MODE == 1) {
                g_attn2[gr * ATTD + n] = v + b1[n];
            } else if constexpr (MODE == 2) {
                g_gpart[ks][gr * G4 + n] = v;
            } else {
                if (t < g_dlen[gr] && n < VV)
                    op[((size_t)gr * TT + t) * VV + n] = v + b1[n];
            }
        }
    }
}

// ================= attention (fused e/softmax/alpha/ctx/emb) =================
__global__ void attention_kernel(const float* __restrict__ enc,
                                 const float* __restrict__ wf,
                                 const float* __restrict__ bfp,
                                 const float* __restrict__ emb_table,
                                 float* __restrict__ out, int t) {
    int b = blockIdx.x;
    if (t >= g_dlen[b]) return;
    int tid = threadIdx.x;
    int warp = tid >> 5, lane = tid & 31;
    __shared__ float s_a2[ATTD];
    __shared__ float s_e[PP];
    __shared__ float s_red[32];

    int cap = g_caps[b * LL + t];
    for (int i = tid; i < EMBD; i += 256)
        g_x[b * XR + i] = emb_table[(size_t)cap * EMBD + i];
    for (int i = tid; i < ATTD; i += 256) s_a2[i] = g_attn2[b * ATTD + i];
    __syncthreads();

    float bfv = bfp[0];
    const float* a1 = g_attn1 + (size_t)b * PP * ATTD;
    for (int p = warp; p < PP; p += 8) {
        const float* row = a1 + (size_t)p * ATTD;
        float s = 0.f;
        for (int a = lane; a < ATTD; a += 32) {
            float v = row[a] + s_a2[a];
            v = fmaxf(v, 0.f);
            s += v * wf[a];
        }
#pragma unroll
        for (int o = 16; o; o >>= 1) s += __shfl_xor_sync(0xffffffffu, s, o);
        if (lane == 0) s_e[p] = s + bfv;
    }
    __syncthreads();

    float mx = -1e30f;
    for (int p = tid; p < PP; p += 256) mx = fmaxf(mx, s_e[p]);
#pragma unroll
    for (int o = 16; o; o >>= 1) mx = fmaxf(mx, __shfl_xor_sync(0xffffffffu, mx, o));
    if (lane == 0) s_red[warp] = mx;
    __syncthreads();
    if (tid == 0) {
        float m2 = s_red[0];
        for (int w = 1; w < 8; w++) m2 = fmaxf(m2, s_red[w]);
        s_red[16] = m2;
    }
    __syncthreads();
    mx = s_red[16];
    float sum = 0.f;
    for (int p = tid; p < PP; p += 256) {
        float e = expf(s_e[p] - mx);
        s_e[p] = e;
        sum += e;
    }
#pragma unroll
    for (int o = 16; o; o >>= 1) sum += __shfl_xor_sync(0xffffffffu, sum, o);
    if (lane == 0) s_red[warp] = sum;
    __syncthreads();
    if (tid == 0) {
        float s2 = 0.f;
        for (int w = 0; w < 8; w++) s2 += s_red[w];
        s_red[17] = 1.f / s2;
    }
    __syncthreads();
    float inv = s_red[17];
    float* aout = out + O_ALPHA + ((size_t)b * TT + t) * PP;
    for (int p = tid; p < PP; p += 256) {
        float al = s_e[p] * inv;
        s_e[p] = al;
        aout[p] = al;
    }
    __syncthreads();

    const float* encb = enc + (size_t)g_sort[b] * (PP * ENCD);
    float acc[8];
#pragma unroll
    for (int j = 0; j < 8; j++) acc[j] = 0.f;
    for (int p = 0; p < PP; p++) {
        float al = s_e[p];
        const float* er = encb + (size_t)p * ENCD;
#pragma unroll
        for (int j = 0; j < 8; j++) acc[j] += al * er[tid + 256 * j];
    }
    float* xo = g_x + b * XR + EMBD;
#pragma unroll
    for (int j = 0; j < 8; j++) xo[tid + 256 * j] = acc[j];
}

// ================= LSTM pointwise (sums split-K partials + biases) ===========
__global__ void lstm_kernel(const float* __restrict__ bih, const float* __restrict__ bhh, int t) {
    int idx = blockIdx.x * blockDim.x + threadIdx.x;
    if (idx >= Bsz * DECD) return;
    int b = idx >> 9;
    if (t >= g_dlen[b]) return;
    int d = idx & 511;
    int base = b * G4;
    float gi = g_gpart[0][base + d]        + g_gpart[1][base + d]        + g_gpart[2][base + d]        + bih[d]        + bhh[d];
    float gf = g_gpart[0][base + d + 512]  + g_gpart[1][base + d + 512]  + g_gpart[2][base + d + 512]  + bih[d + 512]  + bhh[d + 512];
    float gg = g_gpart[0][base + d + 1024] + g_gpart[1][base + d + 1024] + g_gpart[2][base + d + 1024] + bih[d + 1024] + bhh[d + 1024];
    float go = g_gpart[0][base + d + 1536] + g_gpart[1][base + d + 1536] + g_gpart[2][base + d + 1536] + bih[d + 1536] + bhh[d + 1536];
    float c = g_c[idx];
    float cn = sigmf_(gf) * c + sigmf_(gi) * tanhf(gg);
    float hn = sigmf_(go) * tanhf(cn);
    g_c[idx] = cn;
    g_h[idx] = hn;
    g_x[b * XR + 2560 + d] = hn;
}

// ================= launch =================
extern "C" void kernel_launch(void* const* d_in, const int* in_sizes, int n_in,
                              void* d_out, int out_size) {
    const float* enc  = (const float*)d_in[0];
    const int*   caps = (const int*)d_in[1];
    const int*   clen = (const int*)d_in[2];
    const float* embt = (const float*)d_in[3];
    const float* We   = (const float*)d_in[4];
    const float* be   = (const float*)d_in[5];
    const float* Wd   = (const float*)d_in[6];
    const float* bd   = (const float*)d_in[7];
    const float* wf   = (const float*)d_in[8];
    const float* bf   = (const float*)d_in[9];
    const float* Wih  = (const float*)d_in[10];
    const float* bih  = (const float*)d_in[11];
    const float* Whh  = (const float*)d_in[12];
    const float* bhh  = (const float*)d_in[13];
    const float* Wfc  = (const float*)d_in[14];
    const float* bfc  = (const float*)d_in[15];
    float* out = (float*)d_out;

    zero_out_kernel<<<8192, 256>>>((float4*)out);
    zero_state_kernel<<<512, 256>>>();
    sort_kernel<<<1, 128>>>(clen, caps, out);

    // attn1 = enc_sorted @ We + be   (M=25088, N=512)
    mma_gemm<0, ENCD, ENCD, ATTD><<<dim3(8, 196), 256>>>(enc, We, nullptr, be, nullptr, 0);

    for (int t = 0; t < TT; t++) {
        mma_gemm<1, DECD, DECD, ATTD><<<dim3(8, 1), 256>>>(nullptr, Wd, nullptr, bd, nullptr, t);
        attention_kernel<<<128, 256>>>(enc, wf, bf, embt, out, t);
        mma_gemm<2, XR, 1024, 1><<<dim3(32, 3), 256>>>(nullptr, Wih, Whh, nullptr, nullptr, t);
        lstm_kernel<<<256, 256>>>(bih, bhh, t);
        mma_gemm<3, DECD, DECD, VV><<<dim3(469, 1), 256>>>(nullptr, Wfc, nullptr, bfc, out, t);
    }
}

// round 16
// speedup vs baseline: 1.8338x; 1.0628x over previous
#include <cuda_runtime.h>
#include <cuda_bf16.h>
#include <mma.h>
#include <math.h>
#include <stdint.h>

using namespace nvcuda;

#define Bsz 128
#define PP 196
#define ENCD 2048
#define ATTD 512
#define EMBD 512
#define DECD 512
#define VV 30000
#define LL 22
#define TT 21
#define G4 2048
#define XR 3072   // emb(512) | ctx(2048) | h(512)

// output layout offsets (floats): outputs | caps | dec_lens | alphas | sort_ind
#define O_CAPS  80640000ll
#define O_DLEN  80642816ll
#define O_ALPHA 80642944ll
#define O_SORT  81169792ll

__device__ int   g_sort[Bsz];
__device__ int   g_dlen[Bsz];
__device__ int   g_caps[Bsz * LL];
__device__ __align__(16) float g_attn1[(size_t)Bsz * PP * ATTD];
__device__ __align__(16) float g_attn2[Bsz * ATTD];
__device__ __align__(16) float g_h[Bsz * DECD];
__device__ __align__(16) float g_c[Bsz * DECD];
__device__ __align__(16) float g_x[Bsz * XR];
__device__ __align__(16) float g_gpart[3][Bsz * G4];

__device__ __forceinline__ float sigmf_(float x) { return 1.f / (1.f + expf(-x)); }

__device__ __forceinline__ uint32_t pack_hi2(float x, float y) {
    __nv_bfloat162 t;
    t.x = __float2bfloat16(x);
    t.y = __float2bfloat16(y);
    return *reinterpret_cast<uint32_t*>(&t);
}
__device__ __forceinline__ uint32_t pack_lo2(float x, float y) {
    __nv_bfloat16 hx = __float2bfloat16(x), hy = __float2bfloat16(y);
    __nv_bfloat162 t;
    t.x = __float2bfloat16(x - __bfloat162float(hx));
    t.y = __float2bfloat16(y - __bfloat162float(hy));
    return *reinterpret_cast<uint32_t*>(&t);
}

// ================= setup kernels =================
__global__ void zero_out_kernel(float4* out4) {
    const size_t n1 = 20160000u;
    const size_t base2 = 20160736u;
    const size_t n2 = 131712u;
    size_t stride = (size_t)gridDim.x * blockDim.x;
    float4 z = make_float4(0.f, 0.f, 0.f, 0.f);
    for (size_t i = (size_t)blockIdx.x * blockDim.x + threadIdx.x; i < n1 + n2; i += stride) {
        size_t k = (i < n1) ? i : (base2 + (i - n1));
        out4[k] = z;
    }
}

__global__ void zero_state_kernel() {
    int stride = gridDim.x * blockDim.x;
    int i0 = blockIdx.x * blockDim.x + threadIdx.x;
    for (int i = i0; i < Bsz * DECD; i += stride) { g_h[i] = 0.f; g_c[i] = 0.f; }
    for (int i = i0; i < Bsz * XR; i += stride) g_x[i] = 0.f;
}

__global__ void sort_kernel(const int* __restrict__ clen,
                            const int* __restrict__ caps_in,
                            float* __restrict__ out) {
    __shared__ int s_len[Bsz];
    int i = threadIdx.x;
    s_len[i] = clen[i];
    __syncthreads();
    int li = s_len[i];
    int rank = 0;
    for (int j = 0; j < Bsz; j++) {
        int lj = s_len[j];
        rank += (lj > li) || (lj == li && j < i);
    }
    g_sort[rank] = i;
    g_dlen[rank] = li - 1;
    out[O_SORT + rank] = (float)i;
    out[O_DLEN + rank] = (float)(li - 1);
    __syncthreads();
    for (int k = i; k < Bsz * LL; k += Bsz) {
        int b = k / LL, j = k % LL;
        int v = caps_in[g_sort[b] * LL + j];
        g_caps[k] = v;
        out[O_CAPS + k] = (float)v;
    }
}

// ================= WMMA GEMM (R15: software-pipelined staging) ===============
template<int MODE, int KTOT, int KLEN, int NST>
__global__ void __launch_bounds__(256, 2)
mma_gemm(const float* __restrict__ Afp,
         const float* __restrict__ W1, const float* __restrict__ W2,
         const float* __restrict__ b1,
         float* __restrict__ op, int t) {
    __shared__ __align__(16) char smem_raw[32768];
    __nv_bfloat16* sA_hi = (__nv_bfloat16*)smem_raw;   // [128][40]
    __nv_bfloat16* sA_lo = sA_hi + 5120;
    __nv_bfloat16* sB_hi = sA_hi + 10240;              // [64][40]
    __nv_bfloat16* sB_lo = sA_hi + 12800;

    int tid = threadIdx.x, lane = tid & 31, wid = tid >> 5;
    int wm = wid >> 1, wn = wid & 1;
    int n0 = blockIdx.x * 64;
    int m0 = (MODE == 0) ? (int)blockIdx.y * 128 : 0;
    int ks = (MODE == 2) ? (int)blockIdx.y : 0;
    int kbase = ks * KLEN;
    constexpr int NC = KLEN / 32;

    bool my_act = (MODE == 0) ? true : (t < g_dlen[wm * 32]);
    bool row_act[4];
#pragma unroll
    for (int j = 0; j < 4; j++)
        row_act[j] = (MODE == 0) ? true : (t < g_dlen[j * 32]);

    int arow_s = tid >> 3, ac4 = tid & 7;
    const float* aptr[4];
#pragma unroll
    for (int j = 0; j < 4; j++) {
        int row = arow_s + j * 32;
        if constexpr (MODE == 0) {
            int mg = m0 + row;
            aptr[j] = Afp + (size_t)g_sort[mg / PP] * (PP * ENCD) + (size_t)(mg % PP) * ENCD + kbase + ac4 * 4;
        } else if constexpr (MODE == 2) {
            aptr[j] = g_x + (size_t)row * XR + kbase + ac4 * 4;
        } else {
            aptr[j] = g_h + (size_t)row * DECD + kbase + ac4 * 4;
        }
    }
    int offAe[4];
#pragma unroll
    for (int j = 0; j < 4; j++) offAe[j] = (arow_s + j * 32) * 40 + ac4 * 4;

    int bn = tid >> 2;
    int bkq = tid & 3;
    int b2row = tid >> 3, b2c4 = tid & 7;

    wmma::fragment<wmma::accumulator, 16, 16, 16, float> C[2][2];
#pragma unroll
    for (int a = 0; a < 2; a++)
#pragma unroll
        for (int b = 0; b < 2; b++) wmma::fill_fragment(C[a][b], 0.f);

    float4 avr[4];
    float bvr[8];
    float4 b2r[2];

    auto load_chunk = [&](int c) {
        int kc = c * 32;
#pragma unroll
        for (int j = 0; j < 4; j++)
            if (row_act[j]) avr[j] = *(const float4*)(aptr[j] + kc);
        if constexpr (MODE == 2) {
#pragma unroll
            for (int r = 0; r < 2; r++) {
                int row = b2row + r * 32;
                int kg = kbase + kc + b2c4 * 4;
                const float* src = (kg < 2560) ? W1 + (size_t)(n0 + row) * 2560 + kg
                                               : W2 + (size_t)(n0 + row) * 512 + (kg - 2560);
                b2r[r] = *(const float4*)src;
            }
        } else {
            int ng = n0 + bn;
            bool ok = (MODE != 3) || (ng < NST);
            const float* wcol = W1 + (size_t)(kbase + kc + bkq * 8) * NST + ng;
#pragma unroll
            for (int i = 0; i < 8; i++)
                bvr[i] = ok ? wcol[(size_t)i * NST] : 0.f;
        }
    };

    auto store_chunk = [&]() {
#pragma unroll
        for (int j = 0; j < 4; j++) {
            if (row_act[j]) {
                *(uint2*)(sA_hi + offAe[j]) = make_uint2(pack_hi2(avr[j].x, avr[j].y), pack_hi2(avr[j].z, avr[j].w));
                *(uint2*)(sA_lo + offAe[j]) = make_uint2(pack_lo2(avr[j].x, avr[j].y), pack_lo2(avr[j].z, avr[j].w));
            }
        }
        if constexpr (MODE == 2) {
#pragma unroll
            for (int r = 0; r < 2; r++) {
                int row = b2row + r * 32;
                int o = row * 40 + b2c4 * 4;
                *(uint2*)(sB_hi + o) = make_uint2(pack_hi2(b2r[r].x, b2r[r].y), pack_hi2(b2r[r].z, b2r[r].w));
                *(uint2*)(sB_lo + o) = make_uint2(pack_lo2(b2r[r].x, b2r[r].y), pack_lo2(b2r[r].z, b2r[r].w));
            }
        } else {
            uint4 hv, lv;
            hv.x = pack_hi2(bvr[0], bvr[1]); hv.y = pack_hi2(bvr[2], bvr[3]);
            hv.z = pack_hi2(bvr[4], bvr[5]); hv.w = pack_hi2(bvr[6], bvr[7]);
            lv.x = pack_lo2(bvr[0], bvr[1]); lv.y = pack_lo2(bvr[2], bvr[3]);
            lv.z = pack_lo2(bvr[4], bvr[5]); lv.w = pack_lo2(bvr[6], bvr[7]);
            int o = bn * 40 + bkq * 8;
            *(uint4*)(sB_hi + o) = hv;
            *(uint4*)(sB_lo + o) = lv;
        }
    };

    load_chunk(0);

#pragma unroll 1
    for (int c = 0; c < NC; c++) {
        store_chunk();
        __syncthreads();
        if (c + 1 < NC) load_chunk(c + 1);
        if (my_act) {
#pragma unroll
            for (int kk = 0; kk < 2; kk++) {
#pragma unroll
                for (int mf = 0; mf < 2; mf++) {
                    wmma::fragment<wmma::matrix_a, 16, 16, 16, __nv_bfloat16, wmma::row_major> aH, aL;
                    wmma::load_matrix_sync(aH, sA_hi + (wm * 32 + mf * 16) * 40 + kk * 16, 40);
                    wmma::load_matrix_sync(aL, sA_lo + (wm * 32 + mf * 16) * 40 + kk * 16, 40);
#pragma unroll
                    for (int nf = 0; nf < 2; nf++) {
                        wmma::fragment<wmma::matrix_b, 16, 16, 16, __nv_bfloat16, wmma::col_major> bH, bL;
                        wmma::load_matrix_sync(bH, sB_hi + (wn * 32 + nf * 16) * 40 + kk * 16, 40);
                        wmma::load_matrix_sync(bL, sB_lo + (wn * 32 + nf * 16) * 40 + kk * 16, 40);
                        wmma::mma_sync(C[mf][nf], aH, bH, C[mf][nf]);
                        wmma::mma_sync(C[mf][nf], aH, bL, C[mf][nf]);
                        wmma::mma_sync(C[mf][nf], aL, bH, C[mf][nf]);
                    }
                }
            }
        }
        __syncthreads();
    }

    if (my_act) {
        float* stg = (float*)smem_raw + wid * 1024;
        wmma::store_matrix_sync(stg,                C[0][0], 32, wmma::mem_row_major);
        wmma::store_matrix_sync(stg + 16,           C[0][1], 32, wmma::mem_row_major);
        wmma::store_matrix_sync(stg + 16 * 32,      C[1][0], 32, wmma::mem_row_major);
        wmma::store_matrix_sync(stg + 16 * 32 + 16, C[1][1], 32, wmma::mem_row_major);
        __syncwarp();
#pragma unroll 4
        for (int e = lane; e < 1024; e += 32) {
            int rl = e >> 5, cl = e & 31;
            int gr = wm * 32 + rl;
            int n = n0 + wn * 32 + cl;
            float v = stg[e];
            if constexpr (MODE == 0) {
                g_attn1[(size_t)(m0 + gr) * ATTD + n] = v + b1[n];
            } else if constexpr (MODE == 1) {
                g_attn2[gr * ATTD + n] = v + b1[n];
            } else if constexpr (MODE == 2) {
                g_gpart[ks][gr * G4 + n] = v;
            } else {
                if (t < g_dlen[gr] && n < VV)
                    op[((size_t)gr * TT + t) * VV + n] = v + b1[n];
            }
        }
    }
}

// ================= attention (fused e/softmax/alpha/ctx/emb) =================
__global__ void attention_kernel(const float* __restrict__ enc,
                                 const float* __restrict__ wf,
                                 const float* __restrict__ bfp,
                                 const float* __restrict__ emb_table,
                                 float* __restrict__ out, int t) {
    int b = blockIdx.x;
    if (t >= g_dlen[b]) return;
    int tid = threadIdx.x;
    int warp = tid >> 5, lane = tid & 31;
    __shared__ float s_a2[ATTD];
    __shared__ float s_e[PP];
    __shared__ float s_red[32];

    int cap = g_caps[b * LL + t];
    for (int i = tid; i < EMBD; i += 256)
        g_x[b * XR + i] = emb_table[(size_t)cap * EMBD + i];
    for (int i = tid; i < ATTD; i += 256) s_a2[i] = g_attn2[b * ATTD + i];
    __syncthreads();

    float bfv = bfp[0];
    const float* a1 = g_attn1 + (size_t)b * PP * ATTD;
    for (int p = warp; p < PP; p += 8) {
        const float* row = a1 + (size_t)p * ATTD;
        float s = 0.f;
        for (int a = lane; a < ATTD; a += 32) {
            float v = row[a] + s_a2[a];
            v = fmaxf(v, 0.f);
            s += v * wf[a];
        }
#pragma unroll
        for (int o = 16; o; o >>= 1) s += __shfl_xor_sync(0xffffffffu, s, o);
        if (lane == 0) s_e[p] = s + bfv;
    }
    __syncthreads();

    float mx = -1e30f;
    for (int p = tid; p < PP; p += 256) mx = fmaxf(mx, s_e[p]);
#pragma unroll
    for (int o = 16; o; o >>= 1) mx = fmaxf(mx, __shfl_xor_sync(0xffffffffu, mx, o));
    if (lane == 0) s_red[warp] = mx;
    __syncthreads();
    if (tid == 0) {
        float m2 = s_red[0];
        for (int w = 1; w < 8; w++) m2 = fmaxf(m2, s_red[w]);
        s_red[16] = m2;
    }
    __syncthreads();
    mx = s_red[16];
    float sum = 0.f;
    for (int p = tid; p < PP; p += 256) {
        float e = expf(s_e[p] - mx);
        s_e[p] = e;
        sum += e;
    }
#pragma unroll
    for (int o = 16; o; o >>= 1) sum += __shfl_xor_sync(0xffffffffu, sum, o);
    if (lane == 0) s_red[warp] = sum;
    __syncthreads();
    if (tid == 0) {
        float s2 = 0.f;
        for (int w = 0; w < 8; w++) s2 += s_red[w];
        s_red[17] = 1.f / s2;
    }
    __syncthreads();
    float inv = s_red[17];
    float* aout = out + O_ALPHA + ((size_t)b * TT + t) * PP;
    for (int p = tid; p < PP; p += 256) {
        float al = s_e[p] * inv;
        s_e[p] = al;
        aout[p] = al;
    }
    __syncthreads();

    const float* encb = enc + (size_t)g_sort[b] * (PP * ENCD);
    float acc[8];
#pragma unroll
    for (int j = 0; j < 8; j++) acc[j] = 0.f;
    for (int p = 0; p < PP; p++) {
        float al = s_e[p];
        const float* er = encb + (size_t)p * ENCD;
#pragma unroll
        for (int j = 0; j < 8; j++) acc[j] += al * er[tid + 256 * j];
    }
    float* xo = g_x + b * XR + EMBD;
#pragma unroll
    for (int j = 0; j < 8; j++) xo[tid + 256 * j] = acc[j];
}

// ================= LSTM pointwise (sums split-K partials + biases) ===========
__global__ void lstm_kernel(const float* __restrict__ bih, const float* __restrict__ bhh, int t) {
    int idx = blockIdx.x * blockDim.x + threadIdx.x;
    if (idx >= Bsz * DECD) return;
    int b = idx >> 9;
    if (t >= g_dlen[b]) return;
    int d = idx & 511;
    int base = b * G4;
    float gi = g_gpart[0][base + d]        + g_gpart[1][base + d]        + g_gpart[2][base + d]        + bih[d]        + bhh[d];
    float gf = g_gpart[0][base + d + 512]  + g_gpart[1][base + d + 512]  + g_gpart[2][base + d + 512]  + bih[d + 512]  + bhh[d + 512];
    float gg = g_gpart[0][base + d + 1024] + g_gpart[1][base + d + 1024] + g_gpart[2][base + d + 1024] + bih[d + 1024] + bhh[d + 1024];
    float go = g_gpart[0][base + d + 1536] + g_gpart[1][base + d + 1536] + g_gpart[2][base + d + 1536] + bih[d + 1536] + bhh[d + 1536];
    float c = g_c[idx];
    float cn = sigmf_(gf) * c + sigmf_(gi) * tanhf(gg);
    float hn = sigmf_(go) * tanhf(cn);
    g_c[idx] = cn;
    g_h[idx] = hn;
    g_x[b * XR + 2560 + d] = hn;
}

// ================= launch =================
extern "C" void kernel_launch(void* const* d_in, const int* in_sizes, int n_in,
                              void* d_out, int out_size) {
    const float* enc  = (const float*)d_in[0];
    const int*   caps = (const int*)d_in[1];
    const int*   clen = (const int*)d_in[2];
    const float* embt = (const float*)d_in[3];
    const float* We   = (const float*)d_in[4];
    const float* be   = (const float*)d_in[5];
    const float* Wd   = (const float*)d_in[6];
    const float* bd   = (const float*)d_in[7];
    const float* wf   = (const float*)d_in[8];
    const float* bf   = (const float*)d_in[9];
    const float* Wih  = (const float*)d_in[10];
    const float* bih  = (const float*)d_in[11];
    const float* Whh  = (const float*)d_in[12];
    const float* bhh  = (const float*)d_in[13];
    const float* Wfc  = (const float*)d_in[14];
    const float* bfc  = (const float*)d_in[15];
    float* out = (float*)d_out;

    // side stream + events, created once on first (non-capture, correctness) call
    static cudaStream_t s2 = nullptr;
    static cudaEvent_t evZ = nullptr, evL = nullptr, evF = nullptr;
    if (s2 == nullptr) {
        cudaStreamCreateWithFlags(&s2, cudaStreamNonBlocking);
        cudaEventCreateWithFlags(&evZ, cudaEventDisableTiming);
        cudaEventCreateWithFlags(&evL, cudaEventDisableTiming);
        cudaEventCreateWithFlags(&evF, cudaEventDisableTiming);
    }

    // fork: zero_out on s2 (regions disjoint from sort's writes), overlapped with
    // state-zero + sort + attn1 on the main stream
    cudaEventRecord(evZ, 0);                 // fork point: s2 joins capture via this event
    cudaStreamWaitEvent(s2, evZ, 0);
    zero_out_kernel<<<8192, 256, 0, s2>>>((float4*)out);
    cudaEventRecord(evF, s2);                // evF doubles as "zero_out done" before t-loop

    zero_state_kernel<<<512, 256>>>();
    sort_kernel<<<1, 128>>>(clen, caps, out);

    // attn1 = enc_sorted @ We + be   (M=25088, N=512)
    mma_gemm<0, ENCD, ENCD, ATTD><<<dim3(8, 196), 256>>>(enc, We, nullptr, be, nullptr, 0);

    // main stream must see zero_out complete before alphas/outputs are written
    cudaStreamWaitEvent(0, evF, 0);

    for (int t = 0; t < TT; t++) {
        // (t) attention chain on main stream — overlaps fc(t-1) on s2
        mma_gemm<1, DECD, DECD, ATTD><<<dim3(8, 1), 256>>>(nullptr, Wd, nullptr, bd, nullptr, t);
        attention_kernel<<<128, 256>>>(enc, wf, bf, embt, out, t);
        mma_gemm<2, XR, 1024, 1><<<dim3(32, 3), 256>>>(nullptr, Wih, Whh, nullptr, nullptr, t);
        // lstm(t) overwrites g_h -> must wait until fc(t-1) finished reading it
        cudaStreamWaitEvent(0, evF, 0);
        lstm_kernel<<<256, 256>>>(bih, bhh, t);
        cudaEventRecord(evL, 0);
        // fc(t) on s2, after lstm(t)
        cudaStreamWaitEvent(s2, evL, 0);
        mma_gemm<3, DECD, DECD, VV><<<dim3(469, 1), 256, 0, s2>>>(nullptr, Wfc, nullptr, bfc, out, t);
        cudaEventRecord(evF, s2);
    }
    // join: main stream completes only after the last fc
    cudaStreamWaitEvent(0, evF, 0);
}

// round 17
// speedup vs baseline: 2.4265x; 1.3232x over previous
#include <cuda_runtime.h>
#include <cuda_bf16.h>
#include <mma.h>
#include <math.h>
#include <stdint.h>

using namespace nvcuda;

#define Bsz 128
#define PP 196
#define ENCD 2048
#define ATTD 512
#define EMBD 512
#define DECD 512
#define VV 30000
#define LL 22
#define TT 21
#define G4 2048
#define XR 3072   // emb(512) | ctx(2048) | h(512)

// output layout offsets (floats): outputs | caps | dec_lens | alphas | sort_ind
#define O_CAPS  80640000ll
#define O_DLEN  80642816ll
#define O_ALPHA 80642944ll
#define O_SORT  81169792ll

__device__ int   g_sort[Bsz];
__device__ int   g_dlen[Bsz];
__device__ int   g_caps[Bsz * LL];
__device__ __align__(16) float g_attn1[(size_t)Bsz * PP * ATTD];
__device__ __align__(16) float g_attn2[Bsz * ATTD];
__device__ __align__(16) float g_h[Bsz * DECD];
__device__ __align__(16) float g_c[Bsz * DECD];
__device__ __align__(16) float g_x[Bsz * XR];
__device__ __align__(16) float g_gpart[3][Bsz * G4];

__device__ __forceinline__ float sigmf_(float x) { return 1.f / (1.f + expf(-x)); }

__device__ __forceinline__ uint32_t pack_hi2(float x, float y) {
    __nv_bfloat162 t;
    t.x = __float2bfloat16(x);
    t.y = __float2bfloat16(y);
    return *reinterpret_cast<uint32_t*>(&t);
}
__device__ __forceinline__ uint32_t pack_lo2(float x, float y) {
    __nv_bfloat16 hx = __float2bfloat16(x), hy = __float2bfloat16(y);
    __nv_bfloat162 t;
    t.x = __float2bfloat16(x - __bfloat162float(hx));
    t.y = __float2bfloat16(y - __bfloat162float(hy));
    return *reinterpret_cast<uint32_t*>(&t);
}

// ================= setup kernels =================
__global__ void zero_out_kernel(float4* out4) {
    const size_t n1 = 20160000u;
    const size_t base2 = 20160736u;
    const size_t n2 = 131712u;
    size_t stride = (size_t)gridDim.x * blockDim.x;
    float4 z = make_float4(0.f, 0.f, 0.f, 0.f);
    for (size_t i = (size_t)blockIdx.x * blockDim.x + threadIdx.x; i < n1 + n2; i += stride) {
        size_t k = (i < n1) ? i : (base2 + (i - n1));
        out4[k] = z;
    }
}

__global__ void zero_state_kernel() {
    int stride = gridDim.x * blockDim.x;
    int i0 = blockIdx.x * blockDim.x + threadIdx.x;
    for (int i = i0; i < Bsz * DECD; i += stride) { g_h[i] = 0.f; g_c[i] = 0.f; }
    for (int i = i0; i < Bsz * XR; i += stride) g_x[i] = 0.f;
}

__global__ void sort_kernel(const int* __restrict__ clen,
                            const int* __restrict__ caps_in,
                            float* __restrict__ out) {
    __shared__ int s_len[Bsz];
    int i = threadIdx.x;
    s_len[i] = clen[i];
    __syncthreads();
    int li = s_len[i];
    int rank = 0;
    for (int j = 0; j < Bsz; j++) {
        int lj = s_len[j];
        rank += (lj > li) || (lj == li && j < i);
    }
    g_sort[rank] = i;
    g_dlen[rank] = li - 1;
    out[O_SORT + rank] = (float)i;
    out[O_DLEN + rank] = (float)(li - 1);
    __syncthreads();
    for (int k = i; k < Bsz * LL; k += Bsz) {
        int b = k / LL, j = k % LL;
        int v = caps_in[g_sort[b] * LL + j];
        g_caps[k] = v;
        out[O_CAPS + k] = (float)v;
    }
}

// ================= WMMA GEMM (R15: software-pipelined staging) ===============
template<int MODE, int KTOT, int KLEN, int NST>
__global__ void __launch_bounds__(256, 2)
mma_gemm(const float* __restrict__ Afp,
         const float* __restrict__ W1, const float* __restrict__ W2,
         const float* __restrict__ b1,
         float* __restrict__ op, int t) {
    __shared__ __align__(16) char smem_raw[32768];
    __nv_bfloat16* sA_hi = (__nv_bfloat16*)smem_raw;   // [128][40]
    __nv_bfloat16* sA_lo = sA_hi + 5120;
    __nv_bfloat16* sB_hi = sA_hi + 10240;              // [64][40]
    __nv_bfloat16* sB_lo = sA_hi + 12800;

    int tid = threadIdx.x, lane = tid & 31, wid = tid >> 5;
    int wm = wid >> 1, wn = wid & 1;
    int n0 = blockIdx.x * 64;
    int m0 = (MODE == 0) ? (int)blockIdx.y * 128 : 0;
    int ks = (MODE == 2) ? (int)blockIdx.y : 0;
    int kbase = ks * KLEN;
    constexpr int NC = KLEN / 32;

    bool my_act = (MODE == 0) ? true : (t < g_dlen[wm * 32]);
    bool row_act[4];
#pragma unroll
    for (int j = 0; j < 4; j++)
        row_act[j] = (MODE == 0) ? true : (t < g_dlen[j * 32]);

    int arow_s = tid >> 3, ac4 = tid & 7;
    const float* aptr[4];
#pragma unroll
    for (int j = 0; j < 4; j++) {
        int row = arow_s + j * 32;
        if constexpr (MODE == 0) {
            int mg = m0 + row;
            aptr[j] = Afp + (size_t)g_sort[mg / PP] * (PP * ENCD) + (size_t)(mg % PP) * ENCD + kbase + ac4 * 4;
        } else if constexpr (MODE == 2) {
            aptr[j] = g_x + (size_t)row * XR + kbase + ac4 * 4;
        } else {
            aptr[j] = g_h + (size_t)row * DECD + kbase + ac4 * 4;
        }
    }
    int offAe[4];
#pragma unroll
    for (int j = 0; j < 4; j++) offAe[j] = (arow_s + j * 32) * 40 + ac4 * 4;

    int bn = tid >> 2;
    int bkq = tid & 3;
    int b2row = tid >> 3, b2c4 = tid & 7;

    wmma::fragment<wmma::accumulator, 16, 16, 16, float> C[2][2];
#pragma unroll
    for (int a = 0; a < 2; a++)
#pragma unroll
        for (int b = 0; b < 2; b++) wmma::fill_fragment(C[a][b], 0.f);

    float4 avr[4];
    float bvr[8];
    float4 b2r[2];

    auto load_chunk = [&](int c) {
        int kc = c * 32;
#pragma unroll
        for (int j = 0; j < 4; j++)
            if (row_act[j]) avr[j] = *(const float4*)(aptr[j] + kc);
        if constexpr (MODE == 2) {
#pragma unroll
            for (int r = 0; r < 2; r++) {
                int row = b2row + r * 32;
                int kg = kbase + kc + b2c4 * 4;
                const float* src = (kg < 2560) ? W1 + (size_t)(n0 + row) * 2560 + kg
                                               : W2 + (size_t)(n0 + row) * 512 + (kg - 2560);
                b2r[r] = *(const float4*)src;
            }
        } else {
            int ng = n0 + bn;
            bool ok = (MODE != 3) || (ng < NST);
            const float* wcol = W1 + (size_t)(kbase + kc + bkq * 8) * NST + ng;
#pragma unroll
            for (int i = 0; i < 8; i++)
                bvr[i] = ok ? wcol[(size_t)i * NST] : 0.f;
        }
    };

    auto store_chunk = [&]() {
#pragma unroll
        for (int j = 0; j < 4; j++) {
            if (row_act[j]) {
                *(uint2*)(sA_hi + offAe[j]) = make_uint2(pack_hi2(avr[j].x, avr[j].y), pack_hi2(avr[j].z, avr[j].w));
                *(uint2*)(sA_lo + offAe[j]) = make_uint2(pack_lo2(avr[j].x, avr[j].y), pack_lo2(avr[j].z, avr[j].w));
            }
        }
        if constexpr (MODE == 2) {
#pragma unroll
            for (int r = 0; r < 2; r++) {
                int row = b2row + r * 32;
                int o = row * 40 + b2c4 * 4;
                *(uint2*)(sB_hi + o) = make_uint2(pack_hi2(b2r[r].x, b2r[r].y), pack_hi2(b2r[r].z, b2r[r].w));
                *(uint2*)(sB_lo + o) = make_uint2(pack_lo2(b2r[r].x, b2r[r].y), pack_lo2(b2r[r].z, b2r[r].w));
            }
        } else {
            uint4 hv, lv;
            hv.x = pack_hi2(bvr[0], bvr[1]); hv.y = pack_hi2(bvr[2], bvr[3]);
            hv.z = pack_hi2(bvr[4], bvr[5]); hv.w = pack_hi2(bvr[6], bvr[7]);
            lv.x = pack_lo2(bvr[0], bvr[1]); lv.y = pack_lo2(bvr[2], bvr[3]);
            lv.z = pack_lo2(bvr[4], bvr[5]); lv.w = pack_lo2(bvr[6], bvr[7]);
            int o = bn * 40 + bkq * 8;
            *(uint4*)(sB_hi + o) = hv;
            *(uint4*)(sB_lo + o) = lv;
        }
    };

    load_chunk(0);

#pragma unroll 1
    for (int c = 0; c < NC; c++) {
        store_chunk();
        __syncthreads();
        if (c + 1 < NC) load_chunk(c + 1);
        if (my_act) {
#pragma unroll
            for (int kk = 0; kk < 2; kk++) {
#pragma unroll
                for (int mf = 0; mf < 2; mf++) {
                    wmma::fragment<wmma::matrix_a, 16, 16, 16, __nv_bfloat16, wmma::row_major> aH, aL;
                    wmma::load_matrix_sync(aH, sA_hi + (wm * 32 + mf * 16) * 40 + kk * 16, 40);
                    wmma::load_matrix_sync(aL, sA_lo + (wm * 32 + mf * 16) * 40 + kk * 16, 40);
#pragma unroll
                    for (int nf = 0; nf < 2; nf++) {
                        wmma::fragment<wmma::matrix_b, 16, 16, 16, __nv_bfloat16, wmma::col_major> bH, bL;
                        wmma::load_matrix_sync(bH, sB_hi + (wn * 32 + nf * 16) * 40 + kk * 16, 40);
                        wmma::load_matrix_sync(bL, sB_lo + (wn * 32 + nf * 16) * 40 + kk * 16, 40);
                        wmma::mma_sync(C[mf][nf], aH, bH, C[mf][nf]);
                        wmma::mma_sync(C[mf][nf], aH, bL, C[mf][nf]);
                        wmma::mma_sync(C[mf][nf], aL, bH, C[mf][nf]);
                    }
                }
            }
        }
        __syncthreads();
    }

    if (my_act) {
        float* stg = (float*)smem_raw + wid * 1024;
        wmma::store_matrix_sync(stg,                C[0][0], 32, wmma::mem_row_major);
        wmma::store_matrix_sync(stg + 16,           C[0][1], 32, wmma::mem_row_major);
        wmma::store_matrix_sync(stg + 16 * 32,      C[1][0], 32, wmma::mem_row_major);
        wmma::store_matrix_sync(stg + 16 * 32 + 16, C[1][1], 32, wmma::mem_row_major);
        __syncwarp();
#pragma unroll 4
        for (int e = lane; e < 1024; e += 32) {
            int rl = e >> 5, cl = e & 31;
            int gr = wm * 32 + rl;
            int n = n0 + wn * 32 + cl;
            float v = stg[e];
            if constexpr (MODE == 0) {
                g_attn1[(size_t)(m0 + gr) * ATTD + n] = v + b1[n];
            } else if constexpr (MODE == 1) {
                g_attn2[gr * ATTD + n] = v + b1[n];
            } else if constexpr (MODE == 2) {
                g_gpart[ks][gr * G4 + n] = v;
            } else {
                if (t < g_dlen[gr] && n < VV)
                    op[((size_t)gr * TT + t) * VV + n] = v + b1[n];
            }
        }
    }
}

// ================= attention part 1: e, softmax, alpha, emb gather ===========
__global__ void attn_softmax_kernel(const float* __restrict__ wf,
                                    const float* __restrict__ bfp,
                                    const float* __restrict__ emb_table,
                                    float* __restrict__ out, int t) {
    int b = blockIdx.x;
    if (t >= g_dlen[b]) return;
    int tid = threadIdx.x;
    int warp = tid >> 5, lane = tid & 31;
    __shared__ float s_a2[ATTD];
    __shared__ float s_e[PP];
    __shared__ float s_red[32];

    int cap = g_caps[b * LL + t];
    for (int i = tid; i < EMBD; i += 256)
        g_x[b * XR + i] = emb_table[(size_t)cap * EMBD + i];
    for (int i = tid; i < ATTD; i += 256) s_a2[i] = g_attn2[b * ATTD + i];
    __syncthreads();

    float bfv = bfp[0];
    const float* a1 = g_attn1 + (size_t)b * PP * ATTD;
    for (int p = warp; p < PP; p += 8) {
        const float* row = a1 + (size_t)p * ATTD;
        float s = 0.f;
        for (int a = lane; a < ATTD; a += 32) {
            float v = row[a] + s_a2[a];
            v = fmaxf(v, 0.f);
            s += v * wf[a];
        }
#pragma unroll
        for (int o = 16; o; o >>= 1) s += __shfl_xor_sync(0xffffffffu, s, o);
        if (lane == 0) s_e[p] = s + bfv;
    }
    __syncthreads();

    float mx = -1e30f;
    for (int p = tid; p < PP; p += 256) mx = fmaxf(mx, s_e[p]);
#pragma unroll
    for (int o = 16; o; o >>= 1) mx = fmaxf(mx, __shfl_xor_sync(0xffffffffu, mx, o));
    if (lane == 0) s_red[warp] = mx;
    __syncthreads();
    if (tid == 0) {
        float m2 = s_red[0];
        for (int w = 1; w < 8; w++) m2 = fmaxf(m2, s_red[w]);
        s_red[16] = m2;
    }
    __syncthreads();
    mx = s_red[16];
    float sum = 0.f;
    for (int p = tid; p < PP; p += 256) {
        float e = expf(s_e[p] - mx);
        s_e[p] = e;
        sum += e;
    }
#pragma unroll
    for (int o = 16; o; o >>= 1) sum += __shfl_xor_sync(0xffffffffu, sum, o);
    if (lane == 0) s_red[warp] = sum;
    __syncthreads();
    if (tid == 0) {
        float s2 = 0.f;
        for (int w = 0; w < 8; w++) s2 += s_red[w];
        s_red[17] = 1.f / s2;
    }
    __syncthreads();
    float inv = s_red[17];
    float* aout = out + O_ALPHA + ((size_t)b * TT + t) * PP;
    for (int p = tid; p < PP; p += 256)
        aout[p] = s_e[p] * inv;
}

// ================= attention part 2: ctx reduction (8x parallel) =============
// grid (8, 128): chunk of 256 enc-dims x batch; 256 threads, 1 elem each.
__global__ void ctx_kernel(const float* __restrict__ enc,
                           const float* __restrict__ out, int t) {
    int b = blockIdx.y;
    if (t >= g_dlen[b]) return;
    int e0 = blockIdx.x * 256;
    int tid = threadIdx.x;
    __shared__ float s_al[PP];
    const float* aout = out + O_ALPHA + ((size_t)b * TT + t) * PP;
    if (tid < PP) s_al[tid] = aout[tid];
    __syncthreads();

    const float* encb = enc + (size_t)g_sort[b] * (PP * ENCD) + e0 + tid;
    float acc = 0.f;
#pragma unroll 7
    for (int p = 0; p < PP; p++)
        acc += s_al[p] * encb[(size_t)p * ENCD];
    g_x[b * XR + EMBD + e0 + tid] = acc;
}

// ================= LSTM pointwise (sums split-K partials + biases) ===========
__global__ void lstm_kernel(const float* __restrict__ bih, const float* __restrict__ bhh, int t) {
    int idx = blockIdx.x * blockDim.x + threadIdx.x;
    if (idx >= Bsz * DECD) return;
    int b = idx >> 9;
    if (t >= g_dlen[b]) return;
    int d = idx & 511;
    int base = b * G4;
    float gi = g_gpart[0][base + d]        + g_gpart[1][base + d]        + g_gpart[2][base + d]        + bih[d]        + bhh[d];
    float gf = g_gpart[0][base + d + 512]  + g_gpart[1][base + d + 512]  + g_gpart[2][base + d + 512]  + bih[d + 512]  + bhh[d + 512];
    float gg = g_gpart[0][base + d + 1024] + g_gpart[1][base + d + 1024] + g_gpart[2][base + d + 1024] + bih[d + 1024] + bhh[d + 1024];
    float go = g_gpart[0][base + d + 1536] + g_gpart[1][base + d + 1536] + g_gpart[2][base + d + 1536] + bih[d + 1536] + bhh[d + 1536];
    float c = g_c[idx];
    float cn = sigmf_(gf) * c + sigmf_(gi) * tanhf(gg);
    float hn = sigmf_(go) * tanhf(cn);
    g_c[idx] = cn;
    g_h[idx] = hn;
    g_x[b * XR + 2560 + d] = hn;
}

// ================= launch =================
extern "C" void kernel_launch(void* const* d_in, const int* in_sizes, int n_in,
                              void* d_out, int out_size) {
    const float* enc  = (const float*)d_in[0];
    const int*   caps = (const int*)d_in[1];
    const int*   clen = (const int*)d_in[2];
    const float* embt = (const float*)d_in[3];
    const float* We   = (const float*)d_in[4];
    const float* be   = (const float*)d_in[5];
    const float* Wd   = (const float*)d_in[6];
    const float* bd   = (const float*)d_in[7];
    const float* wf   = (const float*)d_in[8];
    const float* bf   = (const float*)d_in[9];
    const float* Wih  = (const float*)d_in[10];
    const float* bih  = (const float*)d_in[11];
    const float* Whh  = (const float*)d_in[12];
    const float* bhh  = (const float*)d_in[13];
    const float* Wfc  = (const float*)d_in[14];
    const float* bfc  = (const float*)d_in[15];
    float* out = (float*)d_out;

    // side stream + events, created once on first (non-capture, correctness) call
    static cudaStream_t s2 = nullptr;
    static cudaEvent_t evZ = nullptr, evL = nullptr, evF = nullptr;
    if (s2 == nullptr) {
        cudaStreamCreateWithFlags(&s2, cudaStreamNonBlocking);
        cudaEventCreateWithFlags(&evZ, cudaEventDisableTiming);
        cudaEventCreateWithFlags(&evL, cudaEventDisableTiming);
        cudaEventCreateWithFlags(&evF, cudaEventDisableTiming);
    }

    // fork: zero_out on s2, overlapped with state-zero + sort + attn1
    cudaEventRecord(evZ, 0);
    cudaStreamWaitEvent(s2, evZ, 0);
    zero_out_kernel<<<8192, 256, 0, s2>>>((float4*)out);
    cudaEventRecord(evF, s2);

    zero_state_kernel<<<512, 256>>>();
    sort_kernel<<<1, 128>>>(clen, caps, out);

    // attn1 = enc_sorted @ We + be   (M=25088, N=512)
    mma_gemm<0, ENCD, ENCD, ATTD><<<dim3(8, 196), 256>>>(enc, We, nullptr, be, nullptr, 0);

    cudaStreamWaitEvent(0, evF, 0);

    for (int t = 0; t < TT; t++) {
        mma_gemm<1, DECD, DECD, ATTD><<<dim3(8, 1), 256>>>(nullptr, Wd, nullptr, bd, nullptr, t);
        attn_softmax_kernel<<<128, 256>>>(wf, bf, embt, out, t);
        ctx_kernel<<<dim3(8, 128), 256>>>(enc, out, t);
        mma_gemm<2, XR, 1024, 1><<<dim3(32, 3), 256>>>(nullptr, Wih, Whh, nullptr, nullptr, t);
        cudaStreamWaitEvent(0, evF, 0);
        lstm_kernel<<<256, 256>>>(bih, bhh, t);
        cudaEventRecord(evL, 0);
        cudaStreamWaitEvent(s2, evL, 0);
        mma_gemm<3, DECD, DECD, VV><<<dim3(469, 1), 256, 0, s2>>>(nullptr, Wfc, nullptr, bfc, out, t);
        cudaEventRecord(evF, s2);
    }
    cudaStreamWaitEvent(0, evF, 0);
}